// round 15
// baseline (speedup 1.0000x reference)
#include <cuda_runtime.h>

#define DIMX   1024
#define HEADS  16
#define DH     64
#define INNER  1024
#define NQKV   3072
#define BATCH  2
#define SEQ    2048
#define ROWS   (BATCH*SEQ)      /* 4096 */
#define BHT    (BATCH*HEADS)    /* 32   */
#define QSCALE 0.125f
#define LN_EPS 1e-5f

/* ------------ scratch (no allocations allowed) ------------ */
__device__ float g_xn  [ROWS*DIMX];
__device__ float g_q   [(size_t)BHT*SEQ*DH];
__device__ float g_k   [(size_t)BHT*SEQ*DH];
__device__ float g_v   [(size_t)BHT*SEQ*DH];
__device__ float g_att [(size_t)ROWS*INNER];
__device__ float g_cs  [2*SEQ*DH];            /* cos | sin table */

/* ---------------- helpers ---------------- */
__device__ __forceinline__ unsigned f2tf(float x) {
    unsigned u;
    asm("cvt.rna.tf32.f32 %0, %1;" : "=r"(u) : "f"(x));
    return u;
}
__device__ __forceinline__ float f2tff(float x) {
    return __uint_as_float(f2tf(x));
}
__device__ __forceinline__ void mma_tf32(float4& c,
                                         unsigned a0, unsigned a1, unsigned a2, unsigned a3,
                                         unsigned b0, unsigned b1) {
    asm("mma.sync.aligned.m16n8k8.row.col.f32.tf32.tf32.f32 "
        "{%0,%1,%2,%3}, {%4,%5,%6,%7}, {%8,%9}, {%0,%1,%2,%3};"
        : "+f"(c.x), "+f"(c.y), "+f"(c.z), "+f"(c.w)
        : "r"(a0), "r"(a1), "r"(a2), "r"(a3), "r"(b0), "r"(b1));
}
__device__ __forceinline__ void cpa16(float* dst, const float* src) {
    unsigned d = (unsigned)__cvta_generic_to_shared(dst);
    asm volatile("cp.async.cg.shared.global [%0], [%1], 16;" :: "r"(d), "l"(src));
}

/* ------------ RoPE sin/cos table (same sincosf -> bit-identical) ------------ */
__global__ void sincos_kernel(const float* __restrict__ pos, float* __restrict__ cs) {
    int i = blockIdx.x*blockDim.x + threadIdx.x;     /* SEQ*DH */
    float s, c;
    sincosf(pos[i], &s, &c);
    cs[i] = c;
    cs[SEQ*DH + i] = s;
}

/* ------- LayerNorm: one WARP per row, shfl-only reduce, 8 rows/block ------- */
__global__ void __launch_bounds__(256) ln_kernel(const float* __restrict__ x,
                                                 const float* __restrict__ w,
                                                 const float* __restrict__ b,
                                                 float* __restrict__ out) {
    int row  = blockIdx.x*8 + (threadIdx.x >> 5);
    int lane = threadIdx.x & 31;
    const float* xr = x + (size_t)row * DIMX;
    float4 xv[8];
    float s = 0.f, ss = 0.f;
    #pragma unroll
    for (int i = 0; i < 8; i++) {
        xv[i] = *(const float4*)(xr + (lane + i*32)*4);
        s  += xv[i].x + xv[i].y + xv[i].z + xv[i].w;
        ss += xv[i].x*xv[i].x + xv[i].y*xv[i].y + xv[i].z*xv[i].z + xv[i].w*xv[i].w;
    }
    #pragma unroll
    for (int o = 16; o; o >>= 1) {
        s  += __shfl_xor_sync(0xffffffffu, s,  o);
        ss += __shfl_xor_sync(0xffffffffu, ss, o);
    }
    float mean = s * (1.0f/DIMX);
    float var  = ss * (1.0f/DIMX) - mean*mean;
    float rstd = rsqrtf(var + LN_EPS);
    float* orow = out + (size_t)row * DIMX;
    #pragma unroll
    for (int i = 0; i < 8; i++) {
        float4 wv = *(const float4*)(w + (lane + i*32)*4);
        float4 bv = *(const float4*)(b + (lane + i*32)*4);
        float4 o;
        o.x = f2tff((xv[i].x-mean)*rstd*wv.x + bv.x);
        o.y = f2tff((xv[i].y-mean)*rstd*wv.y + bv.y);
        o.z = f2tff((xv[i].z-mean)*rstd*wv.z + bv.z);
        o.w = f2tff((xv[i].w-mean)*rstd*wv.w + bv.w);
        *(float4*)(orow + (lane + i*32)*4) = o;
    }
}

/* ===== GEMM machinery: 128x256 block, 256 thr (8 warps, 64x64 each), BK=32,
        2-stage cp.async pipeline. B RAW fp32; cvt.rna on B-fragment path. ===== */
#define GSTAGE 13056           /* floats per stage: 128*36 + 32*264 */

#define GEMM_MAINLOOP(A_, B_, K_, N_)                                          \
    const int nslab = (K_) / 32;                                               \
    _Pragma("unroll")                                                          \
    for (int p = 0; p < 2; p++) {                                              \
        float* sA = dyn + p*GSTAGE;                                            \
        float* sB = sA + 128*36;                                               \
        _Pragma("unroll")                                                      \
        for (int c = 0; c < 4; c++) {                                          \
            int chunk = tid + c*256;                                           \
            int row = chunk >> 3, seg = chunk & 7;                             \
            cpa16(sA + row*36 + seg*4, (A_) + (size_t)row*(K_) + p*32 + seg*4);\
        }                                                                      \
        _Pragma("unroll")                                                      \
        for (int c = 0; c < 8; c++) {                                          \
            int chunk = tid + c*256;                                           \
            int row = chunk >> 6, seg = chunk & 63;                            \
            cpa16(sB + row*264 + seg*4, (B_) + (size_t)(p*32 + row)*(N_) + seg*4);\
        }                                                                      \
        asm volatile("cp.async.commit_group;" ::: "memory");                   \
    }                                                                          \
    for (int sidx = 0; sidx < nslab; sidx++) {                                 \
        asm volatile("cp.async.wait_group 1;" ::: "memory");                   \
        __syncthreads();                                                       \
        const float* sA = dyn + (sidx & 1)*GSTAGE;                             \
        const float* sB = sA + 128*36;                                         \
        _Pragma("unroll")                                                      \
        for (int ks = 0; ks < 4; ks++) {                                       \
            unsigned a[4][4], bf[8][2];                                        \
            _Pragma("unroll")                                                  \
            for (int mt = 0; mt < 4; mt++) {                                   \
                int r = wm*64 + mt*16 + g;                                     \
                a[mt][0] = __float_as_uint(sA[r*36     + ks*8 + t]);           \
                a[mt][1] = __float_as_uint(sA[(r+8)*36 + ks*8 + t]);           \
                a[mt][2] = __float_as_uint(sA[r*36     + ks*8 + t + 4]);       \
                a[mt][3] = __float_as_uint(sA[(r+8)*36 + ks*8 + t + 4]);       \
            }                                                                  \
            _Pragma("unroll")                                                  \
            for (int nt = 0; nt < 8; nt++) {                                   \
                int c = wn*64 + nt*8 + g;                                      \
                bf[nt][0] = f2tf(sB[(ks*8 + t)*264     + c]);                  \
                bf[nt][1] = f2tf(sB[(ks*8 + t + 4)*264 + c]);                  \
            }                                                                  \
            _Pragma("unroll")                                                  \
            for (int mt = 0; mt < 4; mt++)                                     \
                _Pragma("unroll")                                              \
                for (int nt = 0; nt < 8; nt++)                                 \
                    mma_tf32(acc[mt][nt], a[mt][0],a[mt][1],a[mt][2],a[mt][3], \
                             bf[nt][0], bf[nt][1]);                            \
        }                                                                      \
        __syncthreads();                                                       \
        if (sidx + 2 < nslab) {                                                \
            int ns = sidx + 2;                                                 \
            float* sAn = dyn + (ns & 1)*GSTAGE;                                \
            float* sBn = sAn + 128*36;                                         \
            _Pragma("unroll")                                                  \
            for (int c = 0; c < 4; c++) {                                      \
                int chunk = tid + c*256;                                       \
                int row = chunk >> 3, seg = chunk & 7;                         \
                cpa16(sAn + row*36 + seg*4, (A_) + (size_t)row*(K_) + ns*32 + seg*4);\
            }                                                                  \
            _Pragma("unroll")                                                  \
            for (int c = 0; c < 8; c++) {                                      \
                int chunk = tid + c*256;                                       \
                int row = chunk >> 6, seg = chunk & 63;                        \
                cpa16(sBn + row*264 + seg*4, (B_) + (size_t)(ns*32 + row)*(N_) + seg*4);\
            }                                                                  \
        }                                                                      \
        asm volatile("cp.async.commit_group;" ::: "memory");                   \
    }

/* ------- generic GEMM (output projection; B = raw wout) ------- */
__global__ void __launch_bounds__(256, 1) gemm_tf32(const float* __restrict__ A,
                                                    const float* __restrict__ B,
                                                    float* __restrict__ C,
                                                    int N, int K) {
    extern __shared__ float dyn[];
    int tid = threadIdx.x, lane = tid & 31, w = tid >> 5;
    int g = lane >> 2, t = lane & 3;
    int wm = w >> 2, wn = w & 3;                /* 2 x 4 warps, 64x64 each */
    const float* Ab = A + (size_t)blockIdx.y * 128 * K;
    const float* Bb = B + blockIdx.x * 256;
    float4 acc[4][8];
    #pragma unroll
    for (int i = 0; i < 4; i++)
        #pragma unroll
        for (int j = 0; j < 8; j++) acc[i][j] = make_float4(0.f,0.f,0.f,0.f);

    GEMM_MAINLOOP(Ab, Bb, K, N)

    #pragma unroll
    for (int mt = 0; mt < 4; mt++) {
        #pragma unroll
        for (int nt = 0; nt < 8; nt++) {
            int r = blockIdx.y*128 + wm*64 + mt*16 + g;
            int c = blockIdx.x*256 + wn*64 + nt*8 + 2*t;
            *(float2*)(C + (size_t)r*N + c)     = make_float2(acc[mt][nt].x, acc[mt][nt].y);
            *(float2*)(C + (size_t)(r+8)*N + c) = make_float2(acc[mt][nt].z, acc[mt][nt].w);
        }
    }
}

/* ------- QKV GEMM + fully-register RoPE/head-split epilogue -------
   256-wide tile spans 4 heads; each warp's 64-col tile = ONE head, and the
   RoPE partner col d^32 is fragment nt^4 of the SAME thread. No smem staging. */
__global__ void __launch_bounds__(256, 1) gemm_qkv(const float* __restrict__ A,
                                                   const float* __restrict__ B,
                                                   const float* __restrict__ cs,
                                                   float* __restrict__ Qo,
                                                   float* __restrict__ Ko,
                                                   float* __restrict__ Vo) {
    extern __shared__ float dyn[];
    int tid = threadIdx.x, lane = tid & 31, w = tid >> 5;
    int g = lane >> 2, t = lane & 3;
    int wm = w >> 2, wn = w & 3;
    const float* Ab = A + (size_t)blockIdx.y * 128 * DIMX;
    const float* Bb = B + blockIdx.x * 256;
    float4 acc[4][8];
    #pragma unroll
    for (int i = 0; i < 4; i++)
        #pragma unroll
        for (int j = 0; j < 8; j++) acc[i][j] = make_float4(0.f,0.f,0.f,0.f);

    GEMM_MAINLOOP(Ab, Bb, DIMX, NQKV)

    int bx = blockIdx.x;
    int which = bx >> 2;                       /* 0=Q 1=K 2=V */
    float* base = (which == 0) ? Qo : (which == 1) ? Ko : Vo;
    int h = (bx & 3)*4 + wn;
    const float* ctab = cs;
    const float* stab = cs + SEQ*DH;
    float scale = (which == 0) ? QSCALE : 1.0f;
    #pragma unroll
    for (int mt = 0; mt < 4; mt++) {
        #pragma unroll
        for (int rr = 0; rr < 2; rr++) {
            int grow = blockIdx.y*128 + wm*64 + mt*16 + g + rr*8;
            int b = grow >> 11, n = grow & (SEQ-1);
            float* dst = base + ((size_t)(b*HEADS + h)*SEQ + n)*DH;
            #pragma unroll
            for (int nt = 0; nt < 8; nt++) {
                int d = nt*8 + 2*t;
                float vx = rr ? acc[mt][nt].z : acc[mt][nt].x;
                float vy = rr ? acc[mt][nt].w : acc[mt][nt].y;
                float2 o;
                if (which == 2) {
                    o.x = f2tff(vx);
                    o.y = f2tff(vy);
                } else {
                    float px = rr ? acc[mt][nt^4].z : acc[mt][nt^4].x;
                    float py = rr ? acc[mt][nt^4].w : acc[mt][nt^4].y;
                    float sgn = (nt < 4) ? -1.f : 1.f;
                    float2 cv = *(const float2*)(ctab + n*DH + d);
                    float2 sv = *(const float2*)(stab + n*DH + d);
                    o.x = f2tff((vx*cv.x + sgn*px*sv.x) * scale);
                    o.y = f2tff((vy*cv.y + sgn*py*sv.y) * scale);
                }
                *(float2*)(dst + d) = o;
            }
        }
    }
}

/* ---- causal flash attention: 128 q-rows/block, 4 warps x 32 rows (2 m-tiles),
       Q in smem, 2-stage K/V cp.async pipeline (measured best, unchanged) ---- */
#define ASTAGE (64*72*2)       /* floats per K+V stage */
#define QSTRIDE 76             /* bank = (12g+t)%32 — conflict-free */
#define QSM (2*ASTAGE)         /* Q region offset in floats */
__global__ void __launch_bounds__(128, 2) attn_tc(const float* __restrict__ Q,
                                                  const float* __restrict__ K,
                                                  const float* __restrict__ V,
                                                  float* __restrict__ Out) {
    extern __shared__ float dyn[];
    int tid = threadIdx.x;
    int lane = tid & 31, wq = tid >> 5;
    int g = lane >> 2, t = lane & 3;
    int qt = gridDim.x - 1 - blockIdx.x;      /* heavy blocks first */
    int bh = blockIdx.y;
    int q0 = qt * 128;
    const float* Qb = Q + ((size_t)bh*SEQ + q0)*DH;
    const float* Kb = K + (size_t)bh*SEQ*DH;
    const float* Vb = V + (size_t)bh*SEQ*DH;
    float* sQ = dyn + QSM;

    int ntiles = 2*qt + 2;

    /* prologue: Q (persistent) + tile0 -> group0; tile1 -> group1 */
    {
        #pragma unroll
        for (int c = 0; c < 16; c++) {
            int chunk = tid + c*128;
            int row = chunk >> 4, seg = chunk & 15;
            cpa16(sQ + row*QSTRIDE + seg*4, Qb + (size_t)row*DH + seg*4);
        }
        float* sK = dyn;
        float* sV = sK + 64*72;
        #pragma unroll
        for (int c = 0; c < 8; c++) {
            int chunk = tid + c*128;
            int row = chunk >> 4, seg = chunk & 15;
            cpa16(sK + row*72 + seg*4, Kb + (size_t)row*DH + seg*4);
            cpa16(sV + row*72 + seg*4, Vb + (size_t)row*DH + seg*4);
        }
        asm volatile("cp.async.commit_group;" ::: "memory");
        if (ntiles > 1) {
            float* sK1 = dyn + ASTAGE;
            float* sV1 = sK1 + 64*72;
            #pragma unroll
            for (int c = 0; c < 8; c++) {
                int chunk = tid + c*128;
                int row = chunk >> 4, seg = chunk & 15;
                cpa16(sK1 + row*72 + seg*4, Kb + (size_t)(64 + row)*DH + seg*4);
                cpa16(sV1 + row*72 + seg*4, Vb + (size_t)(64 + row)*DH + seg*4);
            }
        }
        asm volatile("cp.async.commit_group;" ::: "memory");
    }

    float m[2][2], l[2][2];
    float4 o[2][8];
    #pragma unroll
    for (int mt = 0; mt < 2; mt++) {
        m[mt][0] = m[mt][1] = -1e30f;
        l[mt][0] = l[mt][1] = 0.f;
        #pragma unroll
        for (int i = 0; i < 8; i++) o[mt][i] = make_float4(0.f,0.f,0.f,0.f);
    }

    int warpRow0 = q0 + wq*32;

    for (int kt = 0; kt < ntiles; kt++) {
        asm volatile("cp.async.wait_group 1;" ::: "memory");
        __syncthreads();

        const float* sK = dyn + (kt & 1)*ASTAGE;
        const float* sV = sK + 64*72;

        /* skip tiles entirely in this warp's masked future (bit-identical) */
        if (kt*64 <= warpRow0 + 31) {
            /* S = Q K^T : Q A-fragments read from smem per (mt,ks) */
            float4 s[2][8];
            #pragma unroll
            for (int mt = 0; mt < 2; mt++)
                #pragma unroll
                for (int i = 0; i < 8; i++) s[mt][i] = make_float4(0.f,0.f,0.f,0.f);
            #pragma unroll
            for (int ks = 0; ks < 8; ks++) {
                unsigned bf[8][2];
                #pragma unroll
                for (int nt = 0; nt < 8; nt++) {
                    bf[nt][0] = __float_as_uint(sK[(nt*8+g)*72 + ks*8 + t]);
                    bf[nt][1] = __float_as_uint(sK[(nt*8+g)*72 + ks*8 + t + 4]);
                }
                #pragma unroll
                for (int mt = 0; mt < 2; mt++) {
                    int lr = wq*32 + mt*16 + g;
                    unsigned a0 = __float_as_uint(sQ[lr*QSTRIDE     + ks*8 + t]);
                    unsigned a1 = __float_as_uint(sQ[(lr+8)*QSTRIDE + ks*8 + t]);
                    unsigned a2 = __float_as_uint(sQ[lr*QSTRIDE     + ks*8 + t + 4]);
                    unsigned a3 = __float_as_uint(sQ[(lr+8)*QSTRIDE + ks*8 + t + 4]);
                    #pragma unroll
                    for (int nt = 0; nt < 8; nt++)
                        mma_tf32(s[mt][nt], a0, a1, a2, a3, bf[nt][0], bf[nt][1]);
                }
            }

            /* causal mask near the diagonal */
            if (kt*64 + 63 > warpRow0) {
                #pragma unroll
                for (int mt = 0; mt < 2; mt++) {
                    int r0g = warpRow0 + mt*16 + g;
                    #pragma unroll
                    for (int nt = 0; nt < 8; nt++) {
                        int c0 = kt*64 + nt*8 + 2*t;
                        if (c0     > r0g)   s[mt][nt].x = -1e30f;
                        if (c0 + 1 > r0g)   s[mt][nt].y = -1e30f;
                        if (c0     > r0g+8) s[mt][nt].z = -1e30f;
                        if (c0 + 1 > r0g+8) s[mt][nt].w = -1e30f;
                    }
                }
            }

            /* online softmax per m-tile */
            #pragma unroll
            for (int mt = 0; mt < 2; mt++) {
                float rm0 = -1e30f, rm1 = -1e30f;
                #pragma unroll
                for (int nt = 0; nt < 8; nt++) {
                    rm0 = fmaxf(rm0, fmaxf(s[mt][nt].x, s[mt][nt].y));
                    rm1 = fmaxf(rm1, fmaxf(s[mt][nt].z, s[mt][nt].w));
                }
                rm0 = fmaxf(rm0, __shfl_xor_sync(0xffffffffu, rm0, 1));
                rm0 = fmaxf(rm0, __shfl_xor_sync(0xffffffffu, rm0, 2));
                rm1 = fmaxf(rm1, __shfl_xor_sync(0xffffffffu, rm1, 1));
                rm1 = fmaxf(rm1, __shfl_xor_sync(0xffffffffu, rm1, 2));
                float mn0 = fmaxf(m[mt][0], rm0), mn1 = fmaxf(m[mt][1], rm1);
                float al0 = __expf(m[mt][0] - mn0), al1 = __expf(m[mt][1] - mn1);
                m[mt][0] = mn0; m[mt][1] = mn1;
                float rs0 = 0.f, rs1 = 0.f;
                #pragma unroll
                for (int nt = 0; nt < 8; nt++) {
                    s[mt][nt].x = __expf(s[mt][nt].x - mn0);
                    s[mt][nt].y = __expf(s[mt][nt].y - mn0);
                    s[mt][nt].z = __expf(s[mt][nt].z - mn1);
                    s[mt][nt].w = __expf(s[mt][nt].w - mn1);
                    rs0 += s[mt][nt].x + s[mt][nt].y;
                    rs1 += s[mt][nt].z + s[mt][nt].w;
                }
                rs0 += __shfl_xor_sync(0xffffffffu, rs0, 1);
                rs0 += __shfl_xor_sync(0xffffffffu, rs0, 2);
                rs1 += __shfl_xor_sync(0xffffffffu, rs1, 1);
                rs1 += __shfl_xor_sync(0xffffffffu, rs1, 2);
                l[mt][0] = l[mt][0]*al0 + rs0;
                l[mt][1] = l[mt][1]*al1 + rs1;
                #pragma unroll
                for (int dn = 0; dn < 8; dn++) {
                    o[mt][dn].x *= al0; o[mt][dn].y *= al0;
                    o[mt][dn].z *= al1; o[mt][dn].w *= al1;
                }
            }

            /* P remap (C-layout -> A fragments via shfl) and O += P V */
            int base = lane & 28;
            int src1 = base | (t >> 1);
            int src2 = src1 + 2;
            bool odd = (t & 1);
            #pragma unroll
            for (int s8 = 0; s8 < 8; s8++) {
                unsigned pa[2][4];
                #pragma unroll
                for (int mt = 0; mt < 2; mt++) {
                    unsigned p0 = f2tf(s[mt][s8].x), p1 = f2tf(s[mt][s8].y);
                    unsigned p2 = f2tf(s[mt][s8].z), p3 = f2tf(s[mt][s8].w);
                    unsigned q00 = __shfl_sync(0xffffffffu, p0, src1);
                    unsigned q01 = __shfl_sync(0xffffffffu, p1, src1);
                    unsigned q10 = __shfl_sync(0xffffffffu, p2, src1);
                    unsigned q11 = __shfl_sync(0xffffffffu, p3, src1);
                    unsigned q20 = __shfl_sync(0xffffffffu, p0, src2);
                    unsigned q21 = __shfl_sync(0xffffffffu, p1, src2);
                    unsigned q30 = __shfl_sync(0xffffffffu, p2, src2);
                    unsigned q31 = __shfl_sync(0xffffffffu, p3, src2);
                    pa[mt][0] = odd ? q01 : q00;
                    pa[mt][1] = odd ? q11 : q10;
                    pa[mt][2] = odd ? q21 : q20;
                    pa[mt][3] = odd ? q31 : q30;
                }
                #pragma unroll
                for (int dn = 0; dn < 8; dn++) {
                    unsigned b0 = __float_as_uint(sV[(s8*8 + t)*72     + dn*8 + g]);
                    unsigned b1 = __float_as_uint(sV[(s8*8 + t + 4)*72 + dn*8 + g]);
                    #pragma unroll
                    for (int mt = 0; mt < 2; mt++)
                        mma_tf32(o[mt][dn], pa[mt][0], pa[mt][1], pa[mt][2], pa[mt][3],
                                 b0, b1);
                }
            }
        }

        /* all warps done reading stage kt&1; refill it with tile kt+2 */
        __syncthreads();
        if (kt + 2 < ntiles) {
            int ns = kt + 2;
            float* sKn = dyn + (ns & 1)*ASTAGE;
            float* sVn = sKn + 64*72;
            #pragma unroll
            for (int c = 0; c < 8; c++) {
                int chunk = tid + c*128;
                int row = chunk >> 4, seg = chunk & 15;
                cpa16(sKn + row*72 + seg*4, Kb + (size_t)(ns*64 + row)*DH + seg*4);
                cpa16(sVn + row*72 + seg*4, Vb + (size_t)(ns*64 + row)*DH + seg*4);
            }
        }
        asm volatile("cp.async.commit_group;" ::: "memory");
    }

    /* epilogue: divide by l, tf32-round, write [b][n][h*d] */
    int b = bh >> 4, h = bh & 15;
    #pragma unroll
    for (int mt = 0; mt < 2; mt++) {
        float inv0 = 1.f / l[mt][0], inv1 = 1.f / l[mt][1];
        int r0 = q0 + wq*32 + mt*16 + g;
        float* ob0 = Out + ((size_t)(b*SEQ + r0))*INNER + h*DH;
        float* ob1 = Out + ((size_t)(b*SEQ + r0 + 8))*INNER + h*DH;
        #pragma unroll
        for (int dn = 0; dn < 8; dn++) {
            int c = dn*8 + 2*t;
            *(float2*)(ob0 + c) = make_float2(f2tff(o[mt][dn].x*inv0), f2tff(o[mt][dn].y*inv0));
            *(float2*)(ob1 + c) = make_float2(f2tff(o[mt][dn].z*inv1), f2tff(o[mt][dn].w*inv1));
        }
    }
}

/* ---------------------------- launch ---------------------------- */
extern "C" void kernel_launch(void* const* d_in, const int* in_sizes, int n_in,
                              void* d_out, int out_size) {
    const float* x    = (const float*)d_in[0];
    const float* pos  = (const float*)d_in[1];
    const float* lnw  = (const float*)d_in[2];
    const float* lnb  = (const float*)d_in[3];
    const float* wqkv = (const float*)d_in[4];
    const float* wout = (const float*)d_in[5];
    float* out = (float*)d_out;

    float *xn, *q, *k, *v, *att, *cs;
    cudaGetSymbolAddress((void**)&xn,  g_xn);
    cudaGetSymbolAddress((void**)&q,   g_q);
    cudaGetSymbolAddress((void**)&k,   g_k);
    cudaGetSymbolAddress((void**)&v,   g_v);
    cudaGetSymbolAddress((void**)&att, g_att);
    cudaGetSymbolAddress((void**)&cs,  g_cs);

    const int gemm_smem = 2 * GSTAGE * 4;                 /* 104448 B */
    const int attn_smem = (2*ASTAGE + 128*QSTRIDE) * 4;   /* 112640 B */
    cudaFuncSetAttribute(gemm_tf32, cudaFuncAttributeMaxDynamicSharedMemorySize, gemm_smem);
    cudaFuncSetAttribute(gemm_qkv,  cudaFuncAttributeMaxDynamicSharedMemorySize, gemm_smem);
    cudaFuncSetAttribute(attn_tc,   cudaFuncAttributeMaxDynamicSharedMemorySize, attn_smem);

    sincos_kernel<<<(SEQ*DH)/256, 256>>>(pos, cs);
    ln_kernel<<<ROWS/8, 256>>>(x, lnw, lnb, xn);
    gemm_qkv<<<dim3(NQKV/256, ROWS/128), 256, gemm_smem>>>(xn, wqkv, cs, q, k, v);
    attn_tc<<<dim3(SEQ/128, BHT), 128, attn_smem>>>(q, k, v, att);
    gemm_tf32<<<dim3(INNER/256, ROWS/128), 256, gemm_smem>>>(att, wout, out, INNER, DIMX);
}

// round 16
// speedup vs baseline: 1.0261x; 1.0261x over previous
#include <cuda_runtime.h>

#define DIMX   1024
#define HEADS  16
#define DH     64
#define INNER  1024
#define NQKV   3072
#define BATCH  2
#define SEQ    2048
#define ROWS   (BATCH*SEQ)      /* 4096 */
#define BHT    (BATCH*HEADS)    /* 32   */
#define QSCALE 0.125f
#define LN_EPS 1e-5f

/* ------------ scratch (no allocations allowed) ------------ */
__device__ float g_xn  [ROWS*DIMX];
__device__ float g_q   [(size_t)BHT*SEQ*DH];
__device__ float g_k   [(size_t)BHT*SEQ*DH];
__device__ float g_v   [(size_t)BHT*SEQ*DH];
__device__ float g_att [(size_t)ROWS*INNER];
__device__ float g_cs  [2*SEQ*DH];            /* cos | sin table */

/* ---------------- helpers ---------------- */
__device__ __forceinline__ unsigned f2tf(float x) {
    unsigned u;
    asm("cvt.rna.tf32.f32 %0, %1;" : "=r"(u) : "f"(x));
    return u;
}
__device__ __forceinline__ float f2tff(float x) {
    return __uint_as_float(f2tf(x));
}
__device__ __forceinline__ void mma_tf32(float4& c,
                                         unsigned a0, unsigned a1, unsigned a2, unsigned a3,
                                         unsigned b0, unsigned b1) {
    asm("mma.sync.aligned.m16n8k8.row.col.f32.tf32.tf32.f32 "
        "{%0,%1,%2,%3}, {%4,%5,%6,%7}, {%8,%9}, {%0,%1,%2,%3};"
        : "+f"(c.x), "+f"(c.y), "+f"(c.z), "+f"(c.w)
        : "r"(a0), "r"(a1), "r"(a2), "r"(a3), "r"(b0), "r"(b1));
}
__device__ __forceinline__ void cpa16(float* dst, const float* src) {
    unsigned d = (unsigned)__cvta_generic_to_shared(dst);
    asm volatile("cp.async.cg.shared.global [%0], [%1], 16;" :: "r"(d), "l"(src));
}

/* ------------ RoPE sin/cos table (same sincosf -> bit-identical) ------------ */
__global__ void sincos_kernel(const float* __restrict__ pos, float* __restrict__ cs) {
    int i = blockIdx.x*blockDim.x + threadIdx.x;     /* SEQ*DH */
    float s, c;
    sincosf(pos[i], &s, &c);
    cs[i] = c;
    cs[SEQ*DH + i] = s;
}

/* ------- LayerNorm: one WARP per row, shfl-only reduce, 8 rows/block ------- */
__global__ void __launch_bounds__(256) ln_kernel(const float* __restrict__ x,
                                                 const float* __restrict__ w,
                                                 const float* __restrict__ b,
                                                 float* __restrict__ out) {
    int row  = blockIdx.x*8 + (threadIdx.x >> 5);
    int lane = threadIdx.x & 31;
    const float* xr = x + (size_t)row * DIMX;
    float4 xv[8];
    float s = 0.f, ss = 0.f;
    #pragma unroll
    for (int i = 0; i < 8; i++) {
        xv[i] = *(const float4*)(xr + (lane + i*32)*4);
        s  += xv[i].x + xv[i].y + xv[i].z + xv[i].w;
        ss += xv[i].x*xv[i].x + xv[i].y*xv[i].y + xv[i].z*xv[i].z + xv[i].w*xv[i].w;
    }
    #pragma unroll
    for (int o = 16; o; o >>= 1) {
        s  += __shfl_xor_sync(0xffffffffu, s,  o);
        ss += __shfl_xor_sync(0xffffffffu, ss, o);
    }
    float mean = s * (1.0f/DIMX);
    float var  = ss * (1.0f/DIMX) - mean*mean;
    float rstd = rsqrtf(var + LN_EPS);
    float* orow = out + (size_t)row * DIMX;
    #pragma unroll
    for (int i = 0; i < 8; i++) {
        float4 wv = *(const float4*)(w + (lane + i*32)*4);
        float4 bv = *(const float4*)(b + (lane + i*32)*4);
        float4 o;
        o.x = f2tff((xv[i].x-mean)*rstd*wv.x + bv.x);
        o.y = f2tff((xv[i].y-mean)*rstd*wv.y + bv.y);
        o.z = f2tff((xv[i].z-mean)*rstd*wv.z + bv.z);
        o.w = f2tff((xv[i].w-mean)*rstd*wv.w + bv.w);
        *(float4*)(orow + (lane + i*32)*4) = o;
    }
}

/* ===== GEMM machinery: 128x128 block, 256 thr (8 warps x 64x32), BK=32,
        3-stage cp.async pipeline. B (weights) RAW fp32; cvt.rna on the
        B-fragment LDS path (identical values to pre-rounding). ===== */
#define GSTAGE 8960            /* floats per stage: 128*36 + 32*136 */

#define GEMM_MAINLOOP(A_, B_, K_, N_)                                          \
    const int nslab = (K_) / 32;                                               \
    _Pragma("unroll")                                                          \
    for (int p = 0; p < 2; p++) {                                              \
        float* sA = dyn + p*GSTAGE;                                            \
        float* sB = sA + 128*36;                                               \
        _Pragma("unroll")                                                      \
        for (int c = 0; c < 4; c++) {                                          \
            int chunk = tid + c*256;                                           \
            int row = chunk >> 3, seg = chunk & 7;                             \
            cpa16(sA + row*36 + seg*4, (A_) + (size_t)row*(K_) + p*32 + seg*4);\
        }                                                                      \
        _Pragma("unroll")                                                      \
        for (int c = 0; c < 4; c++) {                                          \
            int chunk = tid + c*256;                                           \
            int row = chunk >> 5, seg = chunk & 31;                            \
            cpa16(sB + row*136 + seg*4, (B_) + (size_t)(p*32 + row)*(N_) + seg*4);\
        }                                                                      \
        asm volatile("cp.async.commit_group;" ::: "memory");                   \
    }                                                                          \
    int stage = 0;                                                             \
    for (int sidx = 0; sidx < nslab; sidx++) {                                 \
        asm volatile("cp.async.wait_group 1;" ::: "memory");                   \
        __syncthreads();                                                       \
        if (sidx + 2 < nslab) {                                                \
            int ns = sidx + 2;                                                 \
            int nst = ns % 3;                                                  \
            float* sA = dyn + nst*GSTAGE;                                      \
            float* sB = sA + 128*36;                                           \
            _Pragma("unroll")                                                  \
            for (int c = 0; c < 4; c++) {                                      \
                int chunk = tid + c*256;                                       \
                int row = chunk >> 3, seg = chunk & 7;                         \
                cpa16(sA + row*36 + seg*4, (A_) + (size_t)row*(K_) + ns*32 + seg*4);\
            }                                                                  \
            _Pragma("unroll")                                                  \
            for (int c = 0; c < 4; c++) {                                      \
                int chunk = tid + c*256;                                       \
                int row = chunk >> 5, seg = chunk & 31;                        \
                cpa16(sB + row*136 + seg*4, (B_) + (size_t)(ns*32 + row)*(N_) + seg*4);\
            }                                                                  \
        }                                                                      \
        asm volatile("cp.async.commit_group;" ::: "memory");                   \
        const float* sA = dyn + stage*GSTAGE;                                  \
        const float* sB = sA + 128*36;                                         \
        _Pragma("unroll")                                                      \
        for (int ks = 0; ks < 4; ks++) {                                       \
            unsigned a[4][4], bf[4][2];                                        \
            _Pragma("unroll")                                                  \
            for (int mt = 0; mt < 4; mt++) {                                   \
                int r = wm*64 + mt*16 + g;                                     \
                a[mt][0] = __float_as_uint(sA[r*36     + ks*8 + t]);           \
                a[mt][1] = __float_as_uint(sA[(r+8)*36 + ks*8 + t]);           \
                a[mt][2] = __float_as_uint(sA[r*36     + ks*8 + t + 4]);       \
                a[mt][3] = __float_as_uint(sA[(r+8)*36 + ks*8 + t + 4]);       \
            }                                                                  \
            _Pragma("unroll")                                                  \
            for (int nt = 0; nt < 4; nt++) {                                   \
                int c = wn*32 + nt*8 + g;                                      \
                bf[nt][0] = f2tf(sB[(ks*8 + t)*136     + c]);                  \
                bf[nt][1] = f2tf(sB[(ks*8 + t + 4)*136 + c]);                  \
            }                                                                  \
            _Pragma("unroll")                                                  \
            for (int mt = 0; mt < 4; mt++)                                     \
                _Pragma("unroll")                                              \
                for (int nt = 0; nt < 4; nt++)                                 \
                    mma_tf32(acc[mt][nt], a[mt][0],a[mt][1],a[mt][2],a[mt][3], \
                             bf[nt][0], bf[nt][1]);                            \
        }                                                                      \
        stage = (stage + 1 == 3) ? 0 : stage + 1;                              \
    }

/* ------- generic GEMM (output projection; B = raw wout) ------- */
__global__ void __launch_bounds__(256, 2) gemm_tf32(const float* __restrict__ A,
                                                    const float* __restrict__ B,
                                                    float* __restrict__ C,
                                                    int N, int K) {
    extern __shared__ float dyn[];
    int tid = threadIdx.x, lane = tid & 31, w = tid >> 5;
    int g = lane >> 2, t = lane & 3;
    int wm = w >> 2, wn = w & 3;                /* warp tile 64 x 32 */
    const float* Ab = A + (size_t)blockIdx.y * 128 * K;
    const float* Bb = B + blockIdx.x * 128;
    float4 acc[4][4];
    #pragma unroll
    for (int i = 0; i < 4; i++)
        #pragma unroll
        for (int j = 0; j < 4; j++) acc[i][j] = make_float4(0.f,0.f,0.f,0.f);

    GEMM_MAINLOOP(Ab, Bb, K, N)

    #pragma unroll
    for (int mt = 0; mt < 4; mt++) {
        #pragma unroll
        for (int nt = 0; nt < 4; nt++) {
            int r = blockIdx.y*128 + wm*64 + mt*16 + g;
            int c = blockIdx.x*128 + wn*32 + nt*8 + 2*t;
            *(float2*)(C + (size_t)r*N + c)     = make_float2(acc[mt][nt].x, acc[mt][nt].y);
            *(float2*)(C + (size_t)(r+8)*N + c) = make_float2(acc[mt][nt].z, acc[mt][nt].w);
        }
    }
}

/* ------- QKV GEMM (B = raw wqkv) with fused RoPE + head split epilogue ------- */
__global__ void __launch_bounds__(256, 2) gemm_qkv(const float* __restrict__ A,
                                                   const float* __restrict__ B,
                                                   const float* __restrict__ cs,
                                                   float* __restrict__ Qo,
                                                   float* __restrict__ Ko,
                                                   float* __restrict__ Vo) {
    extern __shared__ float dyn[];
    int tid = threadIdx.x, lane = tid & 31, w = tid >> 5;
    int g = lane >> 2, t = lane & 3;
    int wm = w >> 2, wn = w & 3;
    const float* Ab = A + (size_t)blockIdx.y * 128 * DIMX;
    const float* Bb = B + blockIdx.x * 128;
    float4 acc[4][4];
    #pragma unroll
    for (int i = 0; i < 4; i++)
        #pragma unroll
        for (int j = 0; j < 4; j++) acc[i][j] = make_float4(0.f,0.f,0.f,0.f);

    GEMM_MAINLOOP(Ab, Bb, DIMX, NQKV)

    /* stage C tile in smem (reuse pipeline memory; all loads drained) */
    __syncthreads();
    float* sC = dyn;                           /* 128 x 132 */
    #pragma unroll
    for (int mt = 0; mt < 4; mt++) {
        #pragma unroll
        for (int nt = 0; nt < 4; nt++) {
            int r = wm*64 + mt*16 + g;
            int c = wn*32 + nt*8 + 2*t;
            *(float2*)(sC + r*132 + c)     = make_float2(acc[mt][nt].x, acc[mt][nt].y);
            *(float2*)(sC + (r+8)*132 + c) = make_float2(acc[mt][nt].z, acc[mt][nt].w);
        }
    }
    __syncthreads();

    int bx = blockIdx.x;
    int which = bx >> 3;                       /* 0=Q 1=K 2=V */
    int d0 = (tid & 15) * 4;
    float sgn = (d0 < 32) ? -1.f : 1.f;
    const float* ctab = cs;
    const float* stab = cs + SEQ*DH;
    #pragma unroll 4
    for (int it = 0; it < 16; it++) {
        int s = it*16 + (tid >> 4);            /* 0..255 */
        int r = s >> 1, hh = s & 1;
        int grow = blockIdx.y*128 + r;
        int b = grow >> 11, n = grow & (SEQ-1);
        int h = (bx & 7)*2 + hh;
        float4 xv = *(const float4*)(sC + r*132 + hh*64 + d0);
        float* dst;
        float4 o;
        if (which == 2) {
            o.x = f2tff(xv.x); o.y = f2tff(xv.y);
            o.z = f2tff(xv.z); o.w = f2tff(xv.w);
            dst = Vo;
        } else {
            float4 xp = *(const float4*)(sC + r*132 + hh*64 + (d0 ^ 32));
            float4 cv = *(const float4*)(ctab + n*DH + d0);
            float4 sv = *(const float4*)(stab + n*DH + d0);
            if (which == 0) {
                o.x = f2tff((xv.x*cv.x + sgn*xp.x*sv.x) * QSCALE);
                o.y = f2tff((xv.y*cv.y + sgn*xp.y*sv.y) * QSCALE);
                o.z = f2tff((xv.z*cv.z + sgn*xp.z*sv.z) * QSCALE);
                o.w = f2tff((xv.w*cv.w + sgn*xp.w*sv.w) * QSCALE);
                dst = Qo;
            } else {
                o.x = f2tff(xv.x*cv.x + sgn*xp.x*sv.x);
                o.y = f2tff(xv.y*cv.y + sgn*xp.y*sv.y);
                o.z = f2tff(xv.z*cv.z + sgn*xp.z*sv.z);
                o.w = f2tff(xv.w*cv.w + sgn*xp.w*sv.w);
                dst = Ko;
            }
        }
        *(float4*)(dst + ((size_t)(b*HEADS + h)*SEQ + n)*DH + d0) = o;
    }
}

/* ---- causal flash attention: 128 q-rows/block, 4 warps x 32 rows (2 m-tiles),
       Q in smem, 2-stage K/V cp.async pipeline (measured best) ---- */
#define ASTAGE (64*72*2)       /* floats per K+V stage */
#define QSTRIDE 76             /* bank = (12g+t)%32 — conflict-free */
#define QSM (2*ASTAGE)         /* Q region offset in floats */
__global__ void __launch_bounds__(128, 2) attn_tc(const float* __restrict__ Q,
                                                  const float* __restrict__ K,
                                                  const float* __restrict__ V,
                                                  float* __restrict__ Out) {
    extern __shared__ float dyn[];
    int tid = threadIdx.x;
    int lane = tid & 31, wq = tid >> 5;
    int g = lane >> 2, t = lane & 3;
    int qt = gridDim.x - 1 - blockIdx.x;      /* heavy blocks first */
    int bh = blockIdx.y;
    int q0 = qt * 128;
    const float* Qb = Q + ((size_t)bh*SEQ + q0)*DH;
    const float* Kb = K + (size_t)bh*SEQ*DH;
    const float* Vb = V + (size_t)bh*SEQ*DH;
    float* sQ = dyn + QSM;

    int ntiles = 2*qt + 2;

    /* prologue: Q (persistent) + tile0 -> group0; tile1 -> group1 */
    {
        #pragma unroll
        for (int c = 0; c < 16; c++) {
            int chunk = tid + c*128;
            int row = chunk >> 4, seg = chunk & 15;
            cpa16(sQ + row*QSTRIDE + seg*4, Qb + (size_t)row*DH + seg*4);
        }
        float* sK = dyn;
        float* sV = sK + 64*72;
        #pragma unroll
        for (int c = 0; c < 8; c++) {
            int chunk = tid + c*128;
            int row = chunk >> 4, seg = chunk & 15;
            cpa16(sK + row*72 + seg*4, Kb + (size_t)row*DH + seg*4);
            cpa16(sV + row*72 + seg*4, Vb + (size_t)row*DH + seg*4);
        }
        asm volatile("cp.async.commit_group;" ::: "memory");
        if (ntiles > 1) {
            float* sK1 = dyn + ASTAGE;
            float* sV1 = sK1 + 64*72;
            #pragma unroll
            for (int c = 0; c < 8; c++) {
                int chunk = tid + c*128;
                int row = chunk >> 4, seg = chunk & 15;
                cpa16(sK1 + row*72 + seg*4, Kb + (size_t)(64 + row)*DH + seg*4);
                cpa16(sV1 + row*72 + seg*4, Vb + (size_t)(64 + row)*DH + seg*4);
            }
        }
        asm volatile("cp.async.commit_group;" ::: "memory");
    }

    float m[2][2], l[2][2];
    float4 o[2][8];
    #pragma unroll
    for (int mt = 0; mt < 2; mt++) {
        m[mt][0] = m[mt][1] = -1e30f;
        l[mt][0] = l[mt][1] = 0.f;
        #pragma unroll
        for (int i = 0; i < 8; i++) o[mt][i] = make_float4(0.f,0.f,0.f,0.f);
    }

    int warpRow0 = q0 + wq*32;

    for (int kt = 0; kt < ntiles; kt++) {
        asm volatile("cp.async.wait_group 1;" ::: "memory");
        __syncthreads();

        const float* sK = dyn + (kt & 1)*ASTAGE;
        const float* sV = sK + 64*72;

        /* skip tiles entirely in this warp's masked future (bit-identical) */
        if (kt*64 <= warpRow0 + 31) {
            /* S = Q K^T : Q A-fragments read from smem per (mt,ks) */
            float4 s[2][8];
            #pragma unroll
            for (int mt = 0; mt < 2; mt++)
                #pragma unroll
                for (int i = 0; i < 8; i++) s[mt][i] = make_float4(0.f,0.f,0.f,0.f);
            #pragma unroll
            for (int ks = 0; ks < 8; ks++) {
                unsigned bf[8][2];
                #pragma unroll
                for (int nt = 0; nt < 8; nt++) {
                    bf[nt][0] = __float_as_uint(sK[(nt*8+g)*72 + ks*8 + t]);
                    bf[nt][1] = __float_as_uint(sK[(nt*8+g)*72 + ks*8 + t + 4]);
                }
                #pragma unroll
                for (int mt = 0; mt < 2; mt++) {
                    int lr = wq*32 + mt*16 + g;
                    unsigned a0 = __float_as_uint(sQ[lr*QSTRIDE     + ks*8 + t]);
                    unsigned a1 = __float_as_uint(sQ[(lr+8)*QSTRIDE + ks*8 + t]);
                    unsigned a2 = __float_as_uint(sQ[lr*QSTRIDE     + ks*8 + t + 4]);
                    unsigned a3 = __float_as_uint(sQ[(lr+8)*QSTRIDE + ks*8 + t + 4]);
                    #pragma unroll
                    for (int nt = 0; nt < 8; nt++)
                        mma_tf32(s[mt][nt], a0, a1, a2, a3, bf[nt][0], bf[nt][1]);
                }
            }

            /* causal mask near the diagonal */
            if (kt*64 + 63 > warpRow0) {
                #pragma unroll
                for (int mt = 0; mt < 2; mt++) {
                    int r0g = warpRow0 + mt*16 + g;
                    #pragma unroll
                    for (int nt = 0; nt < 8; nt++) {
                        int c0 = kt*64 + nt*8 + 2*t;
                        if (c0     > r0g)   s[mt][nt].x = -1e30f;
                        if (c0 + 1 > r0g)   s[mt][nt].y = -1e30f;
                        if (c0     > r0g+8) s[mt][nt].z = -1e30f;
                        if (c0 + 1 > r0g+8) s[mt][nt].w = -1e30f;
                    }
                }
            }

            /* online softmax per m-tile */
            #pragma unroll
            for (int mt = 0; mt < 2; mt++) {
                float rm0 = -1e30f, rm1 = -1e30f;
                #pragma unroll
                for (int nt = 0; nt < 8; nt++) {
                    rm0 = fmaxf(rm0, fmaxf(s[mt][nt].x, s[mt][nt].y));
                    rm1 = fmaxf(rm1, fmaxf(s[mt][nt].z, s[mt][nt].w));
                }
                rm0 = fmaxf(rm0, __shfl_xor_sync(0xffffffffu, rm0, 1));
                rm0 = fmaxf(rm0, __shfl_xor_sync(0xffffffffu, rm0, 2));
                rm1 = fmaxf(rm1, __shfl_xor_sync(0xffffffffu, rm1, 1));
                rm1 = fmaxf(rm1, __shfl_xor_sync(0xffffffffu, rm1, 2));
                float mn0 = fmaxf(m[mt][0], rm0), mn1 = fmaxf(m[mt][1], rm1);
                float al0 = __expf(m[mt][0] - mn0), al1 = __expf(m[mt][1] - mn1);
                m[mt][0] = mn0; m[mt][1] = mn1;
                float rs0 = 0.f, rs1 = 0.f;
                #pragma unroll
                for (int nt = 0; nt < 8; nt++) {
                    s[mt][nt].x = __expf(s[mt][nt].x - mn0);
                    s[mt][nt].y = __expf(s[mt][nt].y - mn0);
                    s[mt][nt].z = __expf(s[mt][nt].z - mn1);
                    s[mt][nt].w = __expf(s[mt][nt].w - mn1);
                    rs0 += s[mt][nt].x + s[mt][nt].y;
                    rs1 += s[mt][nt].z + s[mt][nt].w;
                }
                rs0 += __shfl_xor_sync(0xffffffffu, rs0, 1);
                rs0 += __shfl_xor_sync(0xffffffffu, rs0, 2);
                rs1 += __shfl_xor_sync(0xffffffffu, rs1, 1);
                rs1 += __shfl_xor_sync(0xffffffffu, rs1, 2);
                l[mt][0] = l[mt][0]*al0 + rs0;
                l[mt][1] = l[mt][1]*al1 + rs1;
                #pragma unroll
                for (int dn = 0; dn < 8; dn++) {
                    o[mt][dn].x *= al0; o[mt][dn].y *= al0;
                    o[mt][dn].z *= al1; o[mt][dn].w *= al1;
                }
            }

            /* P remap (C-layout -> A fragments via shfl) and O += P V */
            int base = lane & 28;
            int src1 = base | (t >> 1);
            int src2 = src1 + 2;
            bool odd = (t & 1);
            #pragma unroll
            for (int s8 = 0; s8 < 8; s8++) {
                unsigned pa[2][4];
                #pragma unroll
                for (int mt = 0; mt < 2; mt++) {
                    unsigned p0 = f2tf(s[mt][s8].x), p1 = f2tf(s[mt][s8].y);
                    unsigned p2 = f2tf(s[mt][s8].z), p3 = f2tf(s[mt][s8].w);
                    unsigned q00 = __shfl_sync(0xffffffffu, p0, src1);
                    unsigned q01 = __shfl_sync(0xffffffffu, p1, src1);
                    unsigned q10 = __shfl_sync(0xffffffffu, p2, src1);
                    unsigned q11 = __shfl_sync(0xffffffffu, p3, src1);
                    unsigned q20 = __shfl_sync(0xffffffffu, p0, src2);
                    unsigned q21 = __shfl_sync(0xffffffffu, p1, src2);
                    unsigned q30 = __shfl_sync(0xffffffffu, p2, src2);
                    unsigned q31 = __shfl_sync(0xffffffffu, p3, src2);
                    pa[mt][0] = odd ? q01 : q00;
                    pa[mt][1] = odd ? q11 : q10;
                    pa[mt][2] = odd ? q21 : q20;
                    pa[mt][3] = odd ? q31 : q30;
                }
                #pragma unroll
                for (int dn = 0; dn < 8; dn++) {
                    unsigned b0 = __float_as_uint(sV[(s8*8 + t)*72     + dn*8 + g]);
                    unsigned b1 = __float_as_uint(sV[(s8*8 + t + 4)*72 + dn*8 + g]);
                    #pragma unroll
                    for (int mt = 0; mt < 2; mt++)
                        mma_tf32(o[mt][dn], pa[mt][0], pa[mt][1], pa[mt][2], pa[mt][3],
                                 b0, b1);
                }
            }
        }

        /* all warps done reading stage kt&1; refill it with tile kt+2 */
        __syncthreads();
        if (kt + 2 < ntiles) {
            int ns = kt + 2;
            float* sKn = dyn + (ns & 1)*ASTAGE;
            float* sVn = sKn + 64*72;
            #pragma unroll
            for (int c = 0; c < 8; c++) {
                int chunk = tid + c*128;
                int row = chunk >> 4, seg = chunk & 15;
                cpa16(sKn + row*72 + seg*4, Kb + (size_t)(ns*64 + row)*DH + seg*4);
                cpa16(sVn + row*72 + seg*4, Vb + (size_t)(ns*64 + row)*DH + seg*4);
            }
        }
        asm volatile("cp.async.commit_group;" ::: "memory");
    }

    /* epilogue: divide by l, tf32-round, write [b][n][h*d] */
    int b = bh >> 4, h = bh & 15;
    #pragma unroll
    for (int mt = 0; mt < 2; mt++) {
        float inv0 = 1.f / l[mt][0], inv1 = 1.f / l[mt][1];
        int r0 = q0 + wq*32 + mt*16 + g;
        float* ob0 = Out + ((size_t)(b*SEQ + r0))*INNER + h*DH;
        float* ob1 = Out + ((size_t)(b*SEQ + r0 + 8))*INNER + h*DH;
        #pragma unroll
        for (int dn = 0; dn < 8; dn++) {
            int c = dn*8 + 2*t;
            *(float2*)(ob0 + c) = make_float2(f2tff(o[mt][dn].x*inv0), f2tff(o[mt][dn].y*inv0));
            *(float2*)(ob1 + c) = make_float2(f2tff(o[mt][dn].z*inv1), f2tff(o[mt][dn].w*inv1));
        }
    }
}

/* ---------------------------- launch ---------------------------- */
extern "C" void kernel_launch(void* const* d_in, const int* in_sizes, int n_in,
                              void* d_out, int out_size) {
    const float* x    = (const float*)d_in[0];
    const float* pos  = (const float*)d_in[1];
    const float* lnw  = (const float*)d_in[2];
    const float* lnb  = (const float*)d_in[3];
    const float* wqkv = (const float*)d_in[4];
    const float* wout = (const float*)d_in[5];
    float* out = (float*)d_out;

    float *xn, *q, *k, *v, *att, *cs;
    cudaGetSymbolAddress((void**)&xn,  g_xn);
    cudaGetSymbolAddress((void**)&q,   g_q);
    cudaGetSymbolAddress((void**)&k,   g_k);
    cudaGetSymbolAddress((void**)&v,   g_v);
    cudaGetSymbolAddress((void**)&att, g_att);
    cudaGetSymbolAddress((void**)&cs,  g_cs);

    const int gemm_smem = 3 * GSTAGE * 4;                 /* 107520 B */
    const int attn_smem = (2*ASTAGE + 128*QSTRIDE) * 4;   /* 112640 B */
    cudaFuncSetAttribute(gemm_tf32, cudaFuncAttributeMaxDynamicSharedMemorySize, gemm_smem);
    cudaFuncSetAttribute(gemm_qkv,  cudaFuncAttributeMaxDynamicSharedMemorySize, gemm_smem);
    cudaFuncSetAttribute(attn_tc,   cudaFuncAttributeMaxDynamicSharedMemorySize, attn_smem);

    sincos_kernel<<<(SEQ*DH)/256, 256>>>(pos, cs);
    ln_kernel<<<ROWS/8, 256>>>(x, lnw, lnb, xn);
    gemm_qkv<<<dim3(NQKV/128, ROWS/128), 256, gemm_smem>>>(xn, wqkv, cs, q, k, v);
    attn_tc<<<dim3(SEQ/128, BHT), 128, attn_smem>>>(q, k, v, att);
    gemm_tf32<<<dim3(INNER/128, ROWS/128), 256, gemm_smem>>>(att, wout, out, INNER, DIMX);
}

// round 17
// speedup vs baseline: 1.0371x; 1.0108x over previous
#include <cuda_runtime.h>

#define DIMX   1024
#define HEADS  16
#define DH     64
#define INNER  1024
#define NQKV   3072
#define BATCH  2
#define SEQ    2048
#define ROWS   (BATCH*SEQ)      /* 4096 */
#define BHT    (BATCH*HEADS)    /* 32   */
#define QSCALE 0.125f
#define LN_EPS 1e-5f

/* ------------ scratch (no allocations allowed) ------------ */
__device__ float g_xn  [ROWS*DIMX];
__device__ float g_q   [(size_t)BHT*SEQ*DH];
__device__ float g_k   [(size_t)BHT*SEQ*DH];
__device__ float g_v   [(size_t)BHT*SEQ*DH];
__device__ float g_att [(size_t)ROWS*INNER];
__device__ float g_cs  [2*SEQ*DH];            /* cos | sin table */

/* ---------------- helpers ---------------- */
__device__ __forceinline__ unsigned f2tf(float x) {
    unsigned u;
    asm("cvt.rna.tf32.f32 %0, %1;" : "=r"(u) : "f"(x));
    return u;
}
__device__ __forceinline__ float f2tff(float x) {
    return __uint_as_float(f2tf(x));
}
__device__ __forceinline__ void mma_tf32(float4& c,
                                         unsigned a0, unsigned a1, unsigned a2, unsigned a3,
                                         unsigned b0, unsigned b1) {
    asm("mma.sync.aligned.m16n8k8.row.col.f32.tf32.tf32.f32 "
        "{%0,%1,%2,%3}, {%4,%5,%6,%7}, {%8,%9}, {%0,%1,%2,%3};"
        : "+f"(c.x), "+f"(c.y), "+f"(c.z), "+f"(c.w)
        : "r"(a0), "r"(a1), "r"(a2), "r"(a3), "r"(b0), "r"(b1));
}
__device__ __forceinline__ void cpa16(float* dst, const float* src) {
    unsigned d = (unsigned)__cvta_generic_to_shared(dst);
    asm volatile("cp.async.cg.shared.global [%0], [%1], 16;" :: "r"(d), "l"(src));
}

/* ------- fused prep: blocks 0..511 = LayerNorm (1 warp/row, 8 rows/block);
          blocks 512..1023 = RoPE sin/cos table. Bit-identical to split. ------- */
__global__ void __launch_bounds__(256) prep_kernel(const float* __restrict__ x,
                                                   const float* __restrict__ w,
                                                   const float* __restrict__ b,
                                                   const float* __restrict__ pos,
                                                   float* __restrict__ out,
                                                   float* __restrict__ cs) {
    if (blockIdx.x >= ROWS/8) {
        int i = (blockIdx.x - ROWS/8)*256 + threadIdx.x;   /* SEQ*DH total */
        float s, c;
        sincosf(pos[i], &s, &c);
        cs[i] = c;
        cs[SEQ*DH + i] = s;
        return;
    }
    int row  = blockIdx.x*8 + (threadIdx.x >> 5);
    int lane = threadIdx.x & 31;
    const float* xr = x + (size_t)row * DIMX;
    float4 xv[8];
    float s = 0.f, ss = 0.f;
    #pragma unroll
    for (int i = 0; i < 8; i++) {
        xv[i] = *(const float4*)(xr + (lane + i*32)*4);
        s  += xv[i].x + xv[i].y + xv[i].z + xv[i].w;
        ss += xv[i].x*xv[i].x + xv[i].y*xv[i].y + xv[i].z*xv[i].z + xv[i].w*xv[i].w;
    }
    #pragma unroll
    for (int o = 16; o; o >>= 1) {
        s  += __shfl_xor_sync(0xffffffffu, s,  o);
        ss += __shfl_xor_sync(0xffffffffu, ss, o);
    }
    float mean = s * (1.0f/DIMX);
    float var  = ss * (1.0f/DIMX) - mean*mean;
    float rstd = rsqrtf(var + LN_EPS);
    float* orow = out + (size_t)row * DIMX;
    #pragma unroll
    for (int i = 0; i < 8; i++) {
        float4 wv = *(const float4*)(w + (lane + i*32)*4);
        float4 bv = *(const float4*)(b + (lane + i*32)*4);
        float4 o;
        o.x = f2tff((xv[i].x-mean)*rstd*wv.x + bv.x);
        o.y = f2tff((xv[i].y-mean)*rstd*wv.y + bv.y);
        o.z = f2tff((xv[i].z-mean)*rstd*wv.z + bv.z);
        o.w = f2tff((xv[i].w-mean)*rstd*wv.w + bv.w);
        *(float4*)(orow + (lane + i*32)*4) = o;
    }
}

/* ===== GEMM machinery: 128x128 block, 256 thr (8 warps x 64x32), BK=32,
        3-stage cp.async pipeline. B (weights) RAW fp32; cvt.rna on the
        B-fragment LDS path (identical values to pre-rounding). ===== */
#define GSTAGE 8960            /* floats per stage: 128*36 + 32*136 */

#define GEMM_MAINLOOP(A_, B_, K_, N_)                                          \
    const int nslab = (K_) / 32;                                               \
    _Pragma("unroll")                                                          \
    for (int p = 0; p < 2; p++) {                                              \
        float* sA = dyn + p*GSTAGE;                                            \
        float* sB = sA + 128*36;                                               \
        _Pragma("unroll")                                                      \
        for (int c = 0; c < 4; c++) {                                          \
            int chunk = tid + c*256;                                           \
            int row = chunk >> 3, seg = chunk & 7;                             \
            cpa16(sA + row*36 + seg*4, (A_) + (size_t)row*(K_) + p*32 + seg*4);\
        }                                                                      \
        _Pragma("unroll")                                                      \
        for (int c = 0; c < 4; c++) {                                          \
            int chunk = tid + c*256;                                           \
            int row = chunk >> 5, seg = chunk & 31;                            \
            cpa16(sB + row*136 + seg*4, (B_) + (size_t)(p*32 + row)*(N_) + seg*4);\
        }                                                                      \
        asm volatile("cp.async.commit_group;" ::: "memory");                   \
    }                                                                          \
    int stage = 0;                                                             \
    for (int sidx = 0; sidx < nslab; sidx++) {                                 \
        asm volatile("cp.async.wait_group 1;" ::: "memory");                   \
        __syncthreads();                                                       \
        if (sidx + 2 < nslab) {                                                \
            int ns = sidx + 2;                                                 \
            int nst = ns % 3;                                                  \
            float* sA = dyn + nst*GSTAGE;                                      \
            float* sB = sA + 128*36;                                           \
            _Pragma("unroll")                                                  \
            for (int c = 0; c < 4; c++) {                                      \
                int chunk = tid + c*256;                                       \
                int row = chunk >> 3, seg = chunk & 7;                         \
                cpa16(sA + row*36 + seg*4, (A_) + (size_t)row*(K_) + ns*32 + seg*4);\
            }                                                                  \
            _Pragma("unroll")                                                  \
            for (int c = 0; c < 4; c++) {                                      \
                int chunk = tid + c*256;                                       \
                int row = chunk >> 5, seg = chunk & 31;                        \
                cpa16(sB + row*136 + seg*4, (B_) + (size_t)(ns*32 + row)*(N_) + seg*4);\
            }                                                                  \
        }                                                                      \
        asm volatile("cp.async.commit_group;" ::: "memory");                   \
        const float* sA = dyn + stage*GSTAGE;                                  \
        const float* sB = sA + 128*36;                                         \
        _Pragma("unroll")                                                      \
        for (int ks = 0; ks < 4; ks++) {                                       \
            unsigned a[4][4], bf[4][2];                                        \
            _Pragma("unroll")                                                  \
            for (int mt = 0; mt < 4; mt++) {                                   \
                int r = wm*64 + mt*16 + g;                                     \
                a[mt][0] = __float_as_uint(sA[r*36     + ks*8 + t]);           \
                a[mt][1] = __float_as_uint(sA[(r+8)*36 + ks*8 + t]);           \
                a[mt][2] = __float_as_uint(sA[r*36     + ks*8 + t + 4]);       \
                a[mt][3] = __float_as_uint(sA[(r+8)*36 + ks*8 + t + 4]);       \
            }                                                                  \
            _Pragma("unroll")                                                  \
            for (int nt = 0; nt < 4; nt++) {                                   \
                int c = wn*32 + nt*8 + g;                                      \
                bf[nt][0] = f2tf(sB[(ks*8 + t)*136     + c]);                  \
                bf[nt][1] = f2tf(sB[(ks*8 + t + 4)*136 + c]);                  \
            }                                                                  \
            _Pragma("unroll")                                                  \
            for (int mt = 0; mt < 4; mt++)                                     \
                _Pragma("unroll")                                              \
                for (int nt = 0; nt < 4; nt++)                                 \
                    mma_tf32(acc[mt][nt], a[mt][0],a[mt][1],a[mt][2],a[mt][3], \
                             bf[nt][0], bf[nt][1]);                            \
        }                                                                      \
        stage = (stage + 1 == 3) ? 0 : stage + 1;                              \
    }

/* ------- generic GEMM (output projection; B = raw wout) ------- */
__global__ void __launch_bounds__(256, 2) gemm_tf32(const float* __restrict__ A,
                                                    const float* __restrict__ B,
                                                    float* __restrict__ C,
                                                    int N, int K) {
    extern __shared__ float dyn[];
    int tid = threadIdx.x, lane = tid & 31, w = tid >> 5;
    int g = lane >> 2, t = lane & 3;
    int wm = w >> 2, wn = w & 3;                /* warp tile 64 x 32 */
    const float* Ab = A + (size_t)blockIdx.y * 128 * K;
    const float* Bb = B + blockIdx.x * 128;
    float4 acc[4][4];
    #pragma unroll
    for (int i = 0; i < 4; i++)
        #pragma unroll
        for (int j = 0; j < 4; j++) acc[i][j] = make_float4(0.f,0.f,0.f,0.f);

    GEMM_MAINLOOP(Ab, Bb, K, N)

    #pragma unroll
    for (int mt = 0; mt < 4; mt++) {
        #pragma unroll
        for (int nt = 0; nt < 4; nt++) {
            int r = blockIdx.y*128 + wm*64 + mt*16 + g;
            int c = blockIdx.x*128 + wn*32 + nt*8 + 2*t;
            *(float2*)(C + (size_t)r*N + c)     = make_float2(acc[mt][nt].x, acc[mt][nt].y);
            *(float2*)(C + (size_t)(r+8)*N + c) = make_float2(acc[mt][nt].z, acc[mt][nt].w);
        }
    }
}

/* ------- QKV GEMM (B = raw wqkv) with fused RoPE + head split epilogue ------- */
__global__ void __launch_bounds__(256, 2) gemm_qkv(const float* __restrict__ A,
                                                   const float* __restrict__ B,
                                                   const float* __restrict__ cs,
                                                   float* __restrict__ Qo,
                                                   float* __restrict__ Ko,
                                                   float* __restrict__ Vo) {
    extern __shared__ float dyn[];
    int tid = threadIdx.x, lane = tid & 31, w = tid >> 5;
    int g = lane >> 2, t = lane & 3;
    int wm = w >> 2, wn = w & 3;
    const float* Ab = A + (size_t)blockIdx.y * 128 * DIMX;
    const float* Bb = B + blockIdx.x * 128;
    float4 acc[4][4];
    #pragma unroll
    for (int i = 0; i < 4; i++)
        #pragma unroll
        for (int j = 0; j < 4; j++) acc[i][j] = make_float4(0.f,0.f,0.f,0.f);

    GEMM_MAINLOOP(Ab, Bb, DIMX, NQKV)

    /* stage C tile in smem (reuse pipeline memory; all loads drained) */
    __syncthreads();
    float* sC = dyn;                           /* 128 x 132 */
    #pragma unroll
    for (int mt = 0; mt < 4; mt++) {
        #pragma unroll
        for (int nt = 0; nt < 4; nt++) {
            int r = wm*64 + mt*16 + g;
            int c = wn*32 + nt*8 + 2*t;
            *(float2*)(sC + r*132 + c)     = make_float2(acc[mt][nt].x, acc[mt][nt].y);
            *(float2*)(sC + (r+8)*132 + c) = make_float2(acc[mt][nt].z, acc[mt][nt].w);
        }
    }
    __syncthreads();

    int bx = blockIdx.x;
    int which = bx >> 3;                       /* 0=Q 1=K 2=V */
    int d0 = (tid & 15) * 4;
    float sgn = (d0 < 32) ? -1.f : 1.f;
    const float* ctab = cs;
    const float* stab = cs + SEQ*DH;
    #pragma unroll 4
    for (int it = 0; it < 16; it++) {
        int s = it*16 + (tid >> 4);            /* 0..255 */
        int r = s >> 1, hh = s & 1;
        int grow = blockIdx.y*128 + r;
        int b = grow >> 11, n = grow & (SEQ-1);
        int h = (bx & 7)*2 + hh;
        float4 xv = *(const float4*)(sC + r*132 + hh*64 + d0);
        float* dst;
        float4 o;
        if (which == 2) {
            o.x = f2tff(xv.x); o.y = f2tff(xv.y);
            o.z = f2tff(xv.z); o.w = f2tff(xv.w);
            dst = Vo;
        } else {
            float4 xp = *(const float4*)(sC + r*132 + hh*64 + (d0 ^ 32));
            float4 cv = *(const float4*)(ctab + n*DH + d0);
            float4 sv = *(const float4*)(stab + n*DH + d0);
            if (which == 0) {
                o.x = f2tff((xv.x*cv.x + sgn*xp.x*sv.x) * QSCALE);
                o.y = f2tff((xv.y*cv.y + sgn*xp.y*sv.y) * QSCALE);
                o.z = f2tff((xv.z*cv.z + sgn*xp.z*sv.z) * QSCALE);
                o.w = f2tff((xv.w*cv.w + sgn*xp.w*sv.w) * QSCALE);
                dst = Qo;
            } else {
                o.x = f2tff(xv.x*cv.x + sgn*xp.x*sv.x);
                o.y = f2tff(xv.y*cv.y + sgn*xp.y*sv.y);
                o.z = f2tff(xv.z*cv.z + sgn*xp.z*sv.z);
                o.w = f2tff(xv.w*cv.w + sgn*xp.w*sv.w);
                dst = Ko;
            }
        }
        *(float4*)(dst + ((size_t)(b*HEADS + h)*SEQ + n)*DH + d0) = o;
    }
}

/* ---- causal flash attention: 128 q-rows/block, 4 warps x 32 rows (2 m-tiles),
       Q in smem, 2-stage K/V cp.async pipeline (measured best) ---- */
#define ASTAGE (64*72*2)       /* floats per K+V stage */
#define QSTRIDE 76             /* bank = (12g+t)%32 — conflict-free */
#define QSM (2*ASTAGE)         /* Q region offset in floats */
__global__ void __launch_bounds__(128, 2) attn_tc(const float* __restrict__ Q,
                                                  const float* __restrict__ K,
                                                  const float* __restrict__ V,
                                                  float* __restrict__ Out) {
    extern __shared__ float dyn[];
    int tid = threadIdx.x;
    int lane = tid & 31, wq = tid >> 5;
    int g = lane >> 2, t = lane & 3;
    int qt = gridDim.x - 1 - blockIdx.x;      /* heavy blocks first */
    int bh = blockIdx.y;
    int q0 = qt * 128;
    const float* Qb = Q + ((size_t)bh*SEQ + q0)*DH;
    const float* Kb = K + (size_t)bh*SEQ*DH;
    const float* Vb = V + (size_t)bh*SEQ*DH;
    float* sQ = dyn + QSM;

    int ntiles = 2*qt + 2;

    /* prologue: Q (persistent) + tile0 -> group0; tile1 -> group1 */
    {
        #pragma unroll
        for (int c = 0; c < 16; c++) {
            int chunk = tid + c*128;
            int row = chunk >> 4, seg = chunk & 15;
            cpa16(sQ + row*QSTRIDE + seg*4, Qb + (size_t)row*DH + seg*4);
        }
        float* sK = dyn;
        float* sV = sK + 64*72;
        #pragma unroll
        for (int c = 0; c < 8; c++) {
            int chunk = tid + c*128;
            int row = chunk >> 4, seg = chunk & 15;
            cpa16(sK + row*72 + seg*4, Kb + (size_t)row*DH + seg*4);
            cpa16(sV + row*72 + seg*4, Vb + (size_t)row*DH + seg*4);
        }
        asm volatile("cp.async.commit_group;" ::: "memory");
        if (ntiles > 1) {
            float* sK1 = dyn + ASTAGE;
            float* sV1 = sK1 + 64*72;
            #pragma unroll
            for (int c = 0; c < 8; c++) {
                int chunk = tid + c*128;
                int row = chunk >> 4, seg = chunk & 15;
                cpa16(sK1 + row*72 + seg*4, Kb + (size_t)(64 + row)*DH + seg*4);
                cpa16(sV1 + row*72 + seg*4, Vb + (size_t)(64 + row)*DH + seg*4);
            }
        }
        asm volatile("cp.async.commit_group;" ::: "memory");
    }

    float m[2][2], l[2][2];
    float4 o[2][8];
    #pragma unroll
    for (int mt = 0; mt < 2; mt++) {
        m[mt][0] = m[mt][1] = -1e30f;
        l[mt][0] = l[mt][1] = 0.f;
        #pragma unroll
        for (int i = 0; i < 8; i++) o[mt][i] = make_float4(0.f,0.f,0.f,0.f);
    }

    int warpRow0 = q0 + wq*32;

    for (int kt = 0; kt < ntiles; kt++) {
        asm volatile("cp.async.wait_group 1;" ::: "memory");
        __syncthreads();

        const float* sK = dyn + (kt & 1)*ASTAGE;
        const float* sV = sK + 64*72;

        /* skip tiles entirely in this warp's masked future (bit-identical) */
        if (kt*64 <= warpRow0 + 31) {
            /* S = Q K^T : Q A-fragments read from smem per (mt,ks) */
            float4 s[2][8];
            #pragma unroll
            for (int mt = 0; mt < 2; mt++)
                #pragma unroll
                for (int i = 0; i < 8; i++) s[mt][i] = make_float4(0.f,0.f,0.f,0.f);
            #pragma unroll
            for (int ks = 0; ks < 8; ks++) {
                unsigned bf[8][2];
                #pragma unroll
                for (int nt = 0; nt < 8; nt++) {
                    bf[nt][0] = __float_as_uint(sK[(nt*8+g)*72 + ks*8 + t]);
                    bf[nt][1] = __float_as_uint(sK[(nt*8+g)*72 + ks*8 + t + 4]);
                }
                #pragma unroll
                for (int mt = 0; mt < 2; mt++) {
                    int lr = wq*32 + mt*16 + g;
                    unsigned a0 = __float_as_uint(sQ[lr*QSTRIDE     + ks*8 + t]);
                    unsigned a1 = __float_as_uint(sQ[(lr+8)*QSTRIDE + ks*8 + t]);
                    unsigned a2 = __float_as_uint(sQ[lr*QSTRIDE     + ks*8 + t + 4]);
                    unsigned a3 = __float_as_uint(sQ[(lr+8)*QSTRIDE + ks*8 + t + 4]);
                    #pragma unroll
                    for (int nt = 0; nt < 8; nt++)
                        mma_tf32(s[mt][nt], a0, a1, a2, a3, bf[nt][0], bf[nt][1]);
                }
            }

            /* causal mask near the diagonal */
            if (kt*64 + 63 > warpRow0) {
                #pragma unroll
                for (int mt = 0; mt < 2; mt++) {
                    int r0g = warpRow0 + mt*16 + g;
                    #pragma unroll
                    for (int nt = 0; nt < 8; nt++) {
                        int c0 = kt*64 + nt*8 + 2*t;
                        if (c0     > r0g)   s[mt][nt].x = -1e30f;
                        if (c0 + 1 > r0g)   s[mt][nt].y = -1e30f;
                        if (c0     > r0g+8) s[mt][nt].z = -1e30f;
                        if (c0 + 1 > r0g+8) s[mt][nt].w = -1e30f;
                    }
                }
            }

            /* online softmax per m-tile */
            #pragma unroll
            for (int mt = 0; mt < 2; mt++) {
                float rm0 = -1e30f, rm1 = -1e30f;
                #pragma unroll
                for (int nt = 0; nt < 8; nt++) {
                    rm0 = fmaxf(rm0, fmaxf(s[mt][nt].x, s[mt][nt].y));
                    rm1 = fmaxf(rm1, fmaxf(s[mt][nt].z, s[mt][nt].w));
                }
                rm0 = fmaxf(rm0, __shfl_xor_sync(0xffffffffu, rm0, 1));
                rm0 = fmaxf(rm0, __shfl_xor_sync(0xffffffffu, rm0, 2));
                rm1 = fmaxf(rm1, __shfl_xor_sync(0xffffffffu, rm1, 1));
                rm1 = fmaxf(rm1, __shfl_xor_sync(0xffffffffu, rm1, 2));
                float mn0 = fmaxf(m[mt][0], rm0), mn1 = fmaxf(m[mt][1], rm1);
                float al0 = __expf(m[mt][0] - mn0), al1 = __expf(m[mt][1] - mn1);
                m[mt][0] = mn0; m[mt][1] = mn1;
                float rs0 = 0.f, rs1 = 0.f;
                #pragma unroll
                for (int nt = 0; nt < 8; nt++) {
                    s[mt][nt].x = __expf(s[mt][nt].x - mn0);
                    s[mt][nt].y = __expf(s[mt][nt].y - mn0);
                    s[mt][nt].z = __expf(s[mt][nt].z - mn1);
                    s[mt][nt].w = __expf(s[mt][nt].w - mn1);
                    rs0 += s[mt][nt].x + s[mt][nt].y;
                    rs1 += s[mt][nt].z + s[mt][nt].w;
                }
                rs0 += __shfl_xor_sync(0xffffffffu, rs0, 1);
                rs0 += __shfl_xor_sync(0xffffffffu, rs0, 2);
                rs1 += __shfl_xor_sync(0xffffffffu, rs1, 1);
                rs1 += __shfl_xor_sync(0xffffffffu, rs1, 2);
                l[mt][0] = l[mt][0]*al0 + rs0;
                l[mt][1] = l[mt][1]*al1 + rs1;
                #pragma unroll
                for (int dn = 0; dn < 8; dn++) {
                    o[mt][dn].x *= al0; o[mt][dn].y *= al0;
                    o[mt][dn].z *= al1; o[mt][dn].w *= al1;
                }
            }

            /* P remap (C-layout -> A fragments via shfl) and O += P V */
            int base = lane & 28;
            int src1 = base | (t >> 1);
            int src2 = src1 + 2;
            bool odd = (t & 1);
            #pragma unroll
            for (int s8 = 0; s8 < 8; s8++) {
                unsigned pa[2][4];
                #pragma unroll
                for (int mt = 0; mt < 2; mt++) {
                    unsigned p0 = f2tf(s[mt][s8].x), p1 = f2tf(s[mt][s8].y);
                    unsigned p2 = f2tf(s[mt][s8].z), p3 = f2tf(s[mt][s8].w);
                    unsigned q00 = __shfl_sync(0xffffffffu, p0, src1);
                    unsigned q01 = __shfl_sync(0xffffffffu, p1, src1);
                    unsigned q10 = __shfl_sync(0xffffffffu, p2, src1);
                    unsigned q11 = __shfl_sync(0xffffffffu, p3, src1);
                    unsigned q20 = __shfl_sync(0xffffffffu, p0, src2);
                    unsigned q21 = __shfl_sync(0xffffffffu, p1, src2);
                    unsigned q30 = __shfl_sync(0xffffffffu, p2, src2);
                    unsigned q31 = __shfl_sync(0xffffffffu, p3, src2);
                    pa[mt][0] = odd ? q01 : q00;
                    pa[mt][1] = odd ? q11 : q10;
                    pa[mt][2] = odd ? q21 : q20;
                    pa[mt][3] = odd ? q31 : q30;
                }
                #pragma unroll
                for (int dn = 0; dn < 8; dn++) {
                    unsigned b0 = __float_as_uint(sV[(s8*8 + t)*72     + dn*8 + g]);
                    unsigned b1 = __float_as_uint(sV[(s8*8 + t + 4)*72 + dn*8 + g]);
                    #pragma unroll
                    for (int mt = 0; mt < 2; mt++)
                        mma_tf32(o[mt][dn], pa[mt][0], pa[mt][1], pa[mt][2], pa[mt][3],
                                 b0, b1);
                }
            }
        }

        /* all warps done reading stage kt&1; refill it with tile kt+2 */
        __syncthreads();
        if (kt + 2 < ntiles) {
            int ns = kt + 2;
            float* sKn = dyn + (ns & 1)*ASTAGE;
            float* sVn = sKn + 64*72;
            #pragma unroll
            for (int c = 0; c < 8; c++) {
                int chunk = tid + c*128;
                int row = chunk >> 4, seg = chunk & 15;
                cpa16(sKn + row*72 + seg*4, Kb + (size_t)(ns*64 + row)*DH + seg*4);
                cpa16(sVn + row*72 + seg*4, Vb + (size_t)(ns*64 + row)*DH + seg*4);
            }
        }
        asm volatile("cp.async.commit_group;" ::: "memory");
    }

    /* epilogue: divide by l, tf32-round, write [b][n][h*d] */
    int b = bh >> 4, h = bh & 15;
    #pragma unroll
    for (int mt = 0; mt < 2; mt++) {
        float inv0 = 1.f / l[mt][0], inv1 = 1.f / l[mt][1];
        int r0 = q0 + wq*32 + mt*16 + g;
        float* ob0 = Out + ((size_t)(b*SEQ + r0))*INNER + h*DH;
        float* ob1 = Out + ((size_t)(b*SEQ + r0 + 8))*INNER + h*DH;
        #pragma unroll
        for (int dn = 0; dn < 8; dn++) {
            int c = dn*8 + 2*t;
            *(float2*)(ob0 + c) = make_float2(f2tff(o[mt][dn].x*inv0), f2tff(o[mt][dn].y*inv0));
            *(float2*)(ob1 + c) = make_float2(f2tff(o[mt][dn].z*inv1), f2tff(o[mt][dn].w*inv1));
        }
    }
}

/* ---------------------------- launch ---------------------------- */
extern "C" void kernel_launch(void* const* d_in, const int* in_sizes, int n_in,
                              void* d_out, int out_size) {
    const float* x    = (const float*)d_in[0];
    const float* pos  = (const float*)d_in[1];
    const float* lnw  = (const float*)d_in[2];
    const float* lnb  = (const float*)d_in[3];
    const float* wqkv = (const float*)d_in[4];
    const float* wout = (const float*)d_in[5];
    float* out = (float*)d_out;

    float *xn, *q, *k, *v, *att, *cs;
    cudaGetSymbolAddress((void**)&xn,  g_xn);
    cudaGetSymbolAddress((void**)&q,   g_q);
    cudaGetSymbolAddress((void**)&k,   g_k);
    cudaGetSymbolAddress((void**)&v,   g_v);
    cudaGetSymbolAddress((void**)&att, g_att);
    cudaGetSymbolAddress((void**)&cs,  g_cs);

    const int gemm_smem = 3 * GSTAGE * 4;                 /* 107520 B */
    const int attn_smem = (2*ASTAGE + 128*QSTRIDE) * 4;   /* 112640 B */
    cudaFuncSetAttribute(gemm_tf32, cudaFuncAttributeMaxDynamicSharedMemorySize, gemm_smem);
    cudaFuncSetAttribute(gemm_qkv,  cudaFuncAttributeMaxDynamicSharedMemorySize, gemm_smem);
    cudaFuncSetAttribute(attn_tc,   cudaFuncAttributeMaxDynamicSharedMemorySize, attn_smem);

    prep_kernel<<<ROWS/8 + (SEQ*DH)/256, 256>>>(x, lnw, lnb, pos, xn, cs);
    gemm_qkv<<<dim3(NQKV/128, ROWS/128), 256, gemm_smem>>>(xn, wqkv, cs, q, k, v);
    attn_tc<<<dim3(SEQ/128, BHT), 128, attn_smem>>>(q, k, v, att);
    gemm_tf32<<<dim3(INNER/128, ROWS/128), 256, gemm_smem>>>(att, wout, out, INNER, DIMX);
}